// round 2
// baseline (speedup 1.0000x reference)
#include <cuda_runtime.h>
#include <stdint.h>

#define BNUM 32
#define PNUM 8732
#define CFG  20          // foreground classes
#define NPAIR (BNUM*CFG) // 640
#define KPRE 256
#define TOPK 200
#define CAP  768

// ------------------------------------------------------------------
// scratch (device globals: no allocation allowed)
// ------------------------------------------------------------------
__device__ uint32_t g_keys[(size_t)NPAIR * PNUM];   // mono(prob) per [b][c][p]
__device__ float4   g_boxes[(size_t)BNUM * PNUM];   // decoded corner boxes

__device__ __forceinline__ uint32_t mono(float f) {
    uint32_t u = __float_as_uint(f);
    return (u & 0x80000000u) ? ~u : (u | 0x80000000u);
}
__device__ __forceinline__ float unmono(uint32_t k) {
    uint32_t u = (k & 0x80000000u) ? (k ^ 0x80000000u) : ~k;
    return __uint_as_float(u);
}

// ------------------------------------------------------------------
// kernel 1: softmax (exact jax.nn.softmax order) + decode
// ------------------------------------------------------------------
__global__ void prep_kernel(const float* __restrict__ loc,
                            const float* __restrict__ conf,
                            const float* __restrict__ prior) {
    int g = blockIdx.x * blockDim.x + threadIdx.x;
    if (g >= BNUM * PNUM) return;
    int b = g / PNUM, p = g % PNUM;

    const float* cp = conf + (size_t)g * 21;
    float x[21];
#pragma unroll
    for (int c = 0; c < 21; c++) x[c] = cp[c];
    float m = x[0];
#pragma unroll
    for (int c = 1; c < 21; c++) m = fmaxf(m, x[c]);
    float e[21];
    float s = 0.f;
#pragma unroll
    for (int c = 0; c < 21; c++) { e[c] = expf(x[c] - m); s += e[c]; }
#pragma unroll
    for (int c = 1; c < 21; c++)
        g_keys[((size_t)b * CFG + (c - 1)) * PNUM + p] = mono(e[c] / s);

    float4 l  = ((const float4*)loc)[g];
    float4 pr = ((const float4*)prior)[p];
    float cx = pr.x + (l.x * 0.1f) * pr.z;
    float cy = pr.y + (l.y * 0.1f) * pr.w;
    float w  = pr.z * expf(l.z * 0.2f);
    float h  = pr.w * expf(l.w * 0.2f);
    float x1 = cx - w * 0.5f;
    float y1 = cy - h * 0.5f;
    g_boxes[g] = make_float4(x1, y1, x1 + w, y1 + h);
}

// ------------------------------------------------------------------
// kernel 2: per (b,c) pair — exact radix-select top-256, rank sort,
// parallel suppression-matrix NMS, emit top-200 rows
// ------------------------------------------------------------------
__global__ __launch_bounds__(256, 5) void topk_nms_kernel(float* __restrict__ out) {
    __shared__ uint32_t           s_buf[2048];   // histogram, then suppression matrix
    __shared__ uint32_t           s_csum[256];
    __shared__ unsigned long long s_cand[CAP];
    __shared__ unsigned long long s_key[KPRE];
    __shared__ float4             s_box[KPRE];
    __shared__ float              s_area[KPRE];
    __shared__ uint32_t           s_keep[8];
    __shared__ uint32_t           s_wpre[8];
    __shared__ uint32_t           s_sel[2];
    __shared__ uint32_t           s_cnt;

    const int pair = blockIdx.x;
    const int b    = pair / CFG;
    const int tid  = threadIdx.x;
    const int wid  = tid >> 5, lane = tid & 31;
    const uint32_t* __restrict__ keys = g_keys + (size_t)pair * PNUM;

    // ---------- exact 3-level radix select: F = key of 256th element ----------
    uint32_t F = 0, n_above = 0;
    for (int level = 0; level < 3; level++) {
        for (int i = tid; i < 2048; i += 256) s_buf[i] = 0;
        __syncthreads();
        for (int p = tid; p < PNUM; p += 256) {
            uint32_t k = keys[p];
            bool part; uint32_t bin;
            if (level == 0)      { part = true;              bin = k >> 21; }
            else if (level == 1) { part = ((k >> 21) == F);  bin = (k >> 10) & 0x7FFu; }
            else                 { part = ((k >> 10) == F);  bin = k & 0x3FFu; }
            if (part) atomicAdd(&s_buf[bin], 1u);
        }
        __syncthreads();
        uint32_t cs = 0;
#pragma unroll
        for (int i = 0; i < 8; i++) cs += s_buf[tid * 8 + i];
        s_csum[tid] = cs;
        __syncthreads();
        if (tid == 0) {
            uint32_t acc = n_above;
            int chunk = 0;
            for (int cg = 255; cg >= 0; cg--) {
                if (acc + s_csum[cg] >= KPRE) { chunk = cg; break; }
                acc += s_csum[cg];
            }
            int b1 = chunk * 8;
            for (int bi = chunk * 8 + 7; bi >= chunk * 8; bi--) {
                if (acc + s_buf[bi] >= KPRE) { b1 = bi; break; }
                acc += s_buf[bi];
            }
            s_sel[0] = (uint32_t)b1; s_sel[1] = acc;
        }
        __syncthreads();
        uint32_t b1 = s_sel[0]; n_above = s_sel[1];
        F = (level == 2) ? ((F << 10) | b1) : ((F << 11) | b1);
    }

    // ---------- gather candidates (key >= F): M ~= 256 ----------
    if (tid == 0) s_cnt = 0;
    __syncthreads();
    for (int p = tid; p < PNUM; p += 256) {
        uint32_t k = keys[p];
        if (k >= F) {
            uint32_t pos = atomicAdd(&s_cnt, 1u);
            if (pos < CAP)
                s_cand[pos] = ((unsigned long long)k << 32) | (uint32_t)(~(uint32_t)p);
        }
    }
    __syncthreads();
    uint32_t M = s_cnt; if (M > CAP) M = CAP;

    // ---------- rank sort: rank = #{j : key_j > key_mine}; keys unique ----------
    for (uint32_t t = tid; t < M; t += 256) {
        unsigned long long mine = s_cand[t];
        uint32_t rank = 0;
        for (uint32_t j = 0; j < M; j++) rank += (s_cand[j] > mine);
        if (rank < KPRE) s_key[rank] = mine;
    }
    __syncthreads();

    // ---------- extract top-256 (rank-ordered) ----------
    unsigned long long key = s_key[tid];
    uint32_t idx = ~(uint32_t)key;
    float scv = unmono((uint32_t)(key >> 32));
    float4 bj = g_boxes[(size_t)b * PNUM + idx];
    float aj = fmaxf(bj.z - bj.x, 0.f) * fmaxf(bj.w - bj.y, 0.f);
    s_box[tid]  = bj;
    s_area[tid] = aj;
    {
        bool valid = scv > 0.01f;
        uint32_t bal = __ballot_sync(0xFFFFFFFFu, valid);
        if (lane == 0) s_keep[wid] = bal;
    }
    // zero suppression matrix (reuse s_buf; histogram phase is done)
    for (int i = tid; i < 2048; i += 256) s_buf[i] = 0;
    __syncthreads();

    // ---------- build 256x256 suppression bitmatrix in parallel ----------
    for (int i = 0; i < KPRE; i++) {
        bool sup = false;
        if (wid * 32 + 31 > i) {              // warp-uniform skip for j<=i warps
            float4 bi = s_box[i];
            float wx = fmaxf(fminf(bi.z, bj.z) - fmaxf(bi.x, bj.x), 0.f);
            float wy = fmaxf(fminf(bi.w, bj.w) - fmaxf(bi.y, bj.y), 0.f);
            float inter = __fmul_rn(wx, wy);
            if (tid > i && inter > 0.f) {
                float uni = __fadd_rn(__fadd_rn(s_area[i], aj), -inter);
                sup = (inter / fmaxf(uni, 1e-9f)) > 0.45f;   // IEEE div, matches jnp
            }
        }
        uint32_t bal = __ballot_sync(0xFFFFFFFFu, sup);
        if (lane == 0) s_buf[i * 8 + wid] = bal;
    }
    __syncthreads();

    // ---------- serial greedy scan on warp 0 (bitwise, no block barriers) ----------
    if (wid == 0) {
        uint32_t kw = (lane < 8) ? s_keep[lane] : 0u;
        for (int i = 0; i < KPRE - 1; i++) {
            uint32_t w = __shfl_sync(0xFFFFFFFFu, kw, i >> 5);
            if ((w >> (i & 31)) & 1u)
                kw &= ~s_buf[i * 8 + (lane & 7)];
        }
        if (lane < 8) s_keep[lane] = kw;
    }
    __syncthreads();

    // ---------- compaction + output ----------
    if (tid == 0) {
        uint32_t a = 0;
#pragma unroll
        for (int w2 = 0; w2 < 8; w2++) { s_wpre[w2] = a; a += __popc(s_keep[w2]); }
    }
    float* op = out + (size_t)pair * (TOPK * 5);
    for (int i = tid; i < TOPK * 5; i += 256) op[i] = 0.f;
    __syncthreads();

    uint32_t kwm = s_keep[wid];
    if ((kwm >> lane) & 1u) {
        uint32_t rank = s_wpre[wid] + __popc(kwm & ((1u << lane) - 1u));
        if (rank < TOPK) {
            float* r = op + (size_t)rank * 5;
            r[0] = scv;
            r[1] = bj.x; r[2] = bj.y; r[3] = bj.z; r[4] = bj.w;
        }
    }
}

// ------------------------------------------------------------------
extern "C" void kernel_launch(void* const* d_in, const int* in_sizes, int n_in,
                              void* d_out, int out_size) {
    const float* loc   = (const float*)d_in[0];
    const float* conf  = (const float*)d_in[1];
    const float* prior = (const float*)d_in[2];
    float* out = (float*)d_out;

    int total = BNUM * PNUM;
    prep_kernel<<<(total + 255) / 256, 256>>>(loc, conf, prior);
    topk_nms_kernel<<<NPAIR, 256>>>(out);
}

// round 3
// speedup vs baseline: 1.1505x; 1.1505x over previous
#include <cuda_runtime.h>
#include <stdint.h>

#define BNUM 32
#define PNUM 8732
#define CFG  20
#define NPAIR (BNUM*CFG)
#define KPRE 256
#define TOPK 200
#define CAP  2048
#define QCAP 1024

typedef unsigned long long u64;

// ------------------------------------------------------------------
__device__ uint32_t g_keys[(size_t)NPAIR * PNUM];   // mono(prob) per [b][c][p]
__device__ float4   g_boxes[(size_t)BNUM * PNUM];   // decoded corner boxes

__device__ __forceinline__ uint32_t mono(float f) {
    uint32_t u = __float_as_uint(f);
    return (u & 0x80000000u) ? ~u : (u | 0x80000000u);
}
__device__ __forceinline__ float unmono(uint32_t k) {
    uint32_t u = (k & 0x80000000u) ? (k ^ 0x80000000u) : ~k;
    return __uint_as_float(u);
}

// ------------------------------------------------------------------
// kernel 1: softmax (exact jax.nn.softmax order) + decode
// ------------------------------------------------------------------
__global__ void prep_kernel(const float* __restrict__ loc,
                            const float* __restrict__ conf,
                            const float* __restrict__ prior) {
    int g = blockIdx.x * blockDim.x + threadIdx.x;
    if (g >= BNUM * PNUM) return;
    int b = g / PNUM, p = g % PNUM;

    const float* cp = conf + (size_t)g * 21;
    float x[21];
#pragma unroll
    for (int c = 0; c < 21; c++) x[c] = cp[c];
    float m = x[0];
#pragma unroll
    for (int c = 1; c < 21; c++) m = fmaxf(m, x[c]);
    float e[21];
    float s = 0.f;
#pragma unroll
    for (int c = 0; c < 21; c++) { e[c] = expf(x[c] - m); s += e[c]; }
#pragma unroll
    for (int c = 1; c < 21; c++)
        g_keys[((size_t)b * CFG + (c - 1)) * PNUM + p] = mono(e[c] / s);

    float4 l  = ((const float4*)loc)[g];
    float4 pr = ((const float4*)prior)[p];
    float cx = pr.x + (l.x * 0.1f) * pr.z;
    float cy = pr.y + (l.y * 0.1f) * pr.w;
    float w  = pr.z * expf(l.z * 0.2f);
    float h  = pr.w * expf(l.w * 0.2f);
    float x1 = cx - w * 0.5f;
    float y1 = cy - h * 0.5f;
    g_boxes[g] = make_float4(x1, y1, x1 + w, y1 + h);
}

// ------------------------------------------------------------------
// kernel 2
// ------------------------------------------------------------------
__global__ __launch_bounds__(256, 5) void topk_nms_kernel(float* __restrict__ out) {
    __shared__ u64                s_h64[1024];     // hist (2048 u32) / compacted cands / supp matrix
    __shared__ uint32_t           s_csum[256];
    __shared__ u64                s_cand[CAP];
    __shared__ u64                s_key[KPRE];
    __shared__ float4             s_box[KPRE];
    __shared__ float              s_area[KPRE];
    __shared__ uint32_t           s_keep[8];
    __shared__ uint32_t           s_wpre[8];
    __shared__ uint32_t           s_sel[2];
    __shared__ uint32_t           s_cnt;
    uint32_t* s_hist = (uint32_t*)s_h64;

    const int pair = blockIdx.x;
    const int b    = pair / CFG;
    const int tid  = threadIdx.x;
    const int wid  = tid >> 5, lane = tid & 31;
    const uint32_t* __restrict__ keys = g_keys + (size_t)pair * PNUM;
    const uint4* __restrict__ keys4 = (const uint4*)keys;
    const int N4 = PNUM / 4;  // 2183

    // ================= level-0 histogram (top 11 bits), vectorized =================
    for (int i = tid; i < 2048; i += 256) s_hist[i] = 0;
    __syncthreads();
    for (int p = tid; p < N4; p += 256) {
        uint4 k = keys4[p];
        atomicAdd(&s_hist[k.x >> 21], 1u);
        atomicAdd(&s_hist[k.y >> 21], 1u);
        atomicAdd(&s_hist[k.z >> 21], 1u);
        atomicAdd(&s_hist[k.w >> 21], 1u);
    }
    __syncthreads();
    {
        uint32_t cs = 0;
#pragma unroll
        for (int i = 0; i < 8; i++) cs += s_hist[tid * 8 + i];
        s_csum[tid] = cs;
    }
    __syncthreads();
    if (tid == 0) {
        uint32_t acc = 0; int chunk = 0;
        for (int cg = 255; cg >= 0; cg--) {
            if (acc + s_csum[cg] >= KPRE) { chunk = cg; break; }
            acc += s_csum[cg];
        }
        int bb = chunk * 8;
        for (int bi = chunk * 8 + 7; bi >= chunk * 8; bi--) {
            if (acc + s_hist[bi] >= KPRE) { bb = bi; break; }
            acc += s_hist[bi];
        }
        s_sel[0] = (uint32_t)bb; s_sel[1] = acc;
    }
    __syncthreads();
    uint32_t pref = s_sel[0], n_above = s_sel[1];   // prefix = 11 bits
    uint32_t prefLen = 11;

    // ================= gather: key>>21 >= pref =================
    if (tid == 0) s_cnt = 0;
    __syncthreads();
#define TRYPUSH(kk, pp) \
    if (((kk) >> 21) >= pref) { \
        uint32_t pos = atomicAdd(&s_cnt, 1u); \
        if (pos < CAP) s_cand[pos] = ((u64)(kk) << 32) | (uint32_t)(~(uint32_t)(pp)); }
    for (int p = tid; p < N4; p += 256) {
        uint4 k = keys4[p];
        int p0 = 4 * p;
        TRYPUSH(k.x, p0);
        TRYPUSH(k.y, p0 + 1);
        TRYPUSH(k.z, p0 + 2);
        TRYPUSH(k.w, p0 + 3);
    }
#undef TRYPUSH
    __syncthreads();
    uint32_t M = s_cnt;

    // ---------- fallback (never taken for this data): refine globally at 21 bits ----------
    if (M > CAP) {
        for (int i = tid; i < 2048; i += 256) s_hist[i] = 0;
        __syncthreads();
        for (int p = tid; p < PNUM; p += 256) {
            uint32_t k = keys[p];
            if ((k >> 21) == pref) atomicAdd(&s_hist[(k >> 10) & 0x7FFu], 1u);
        }
        __syncthreads();
        uint32_t cs = 0;
#pragma unroll
        for (int i = 0; i < 8; i++) cs += s_hist[tid * 8 + i];
        s_csum[tid] = cs;
        __syncthreads();
        if (tid == 0) {
            uint32_t acc = n_above; int chunk = 0;
            for (int cg = 255; cg >= 0; cg--) {
                if (acc + s_csum[cg] >= KPRE) { chunk = cg; break; }
                acc += s_csum[cg];
            }
            int bb = chunk * 8;
            for (int bi = chunk * 8 + 7; bi >= chunk * 8; bi--) {
                if (acc + s_hist[bi] >= KPRE) { bb = bi; break; }
                acc += s_hist[bi];
            }
            s_sel[0] = (uint32_t)bb; s_sel[1] = acc;
        }
        __syncthreads();
        pref = (pref << 11) | s_sel[0]; n_above = s_sel[1]; prefLen = 21;
        if (tid == 0) s_cnt = 0;
        __syncthreads();
        for (int p = tid; p < PNUM; p += 256) {
            uint32_t k = keys[p];
            if ((k >> 10) >= pref) {
                uint32_t pos = atomicAdd(&s_cnt, 1u);
                if (pos < CAP) s_cand[pos] = ((u64)k << 32) | (uint32_t)(~(uint32_t)p);
            }
        }
        __syncthreads();
        M = s_cnt;
        if (M > CAP) M = CAP;
    }

    // ================= in-shared refine to exact 32-bit threshold F =================
    if (prefLen == 11) {   // refine bits [20:10]
        for (int i = tid; i < 2048; i += 256) s_hist[i] = 0;
        __syncthreads();
        for (uint32_t i = tid; i < M; i += 256) {
            uint32_t k = (uint32_t)(s_cand[i] >> 32);
            if ((k >> 21) == pref) atomicAdd(&s_hist[(k >> 10) & 0x7FFu], 1u);
        }
        __syncthreads();
        uint32_t cs = 0;
#pragma unroll
        for (int i = 0; i < 8; i++) cs += s_hist[tid * 8 + i];
        s_csum[tid] = cs;
        __syncthreads();
        if (tid == 0) {
            uint32_t acc = n_above; int chunk = 0;
            for (int cg = 255; cg >= 0; cg--) {
                if (acc + s_csum[cg] >= KPRE) { chunk = cg; break; }
                acc += s_csum[cg];
            }
            int bb = chunk * 8;
            for (int bi = chunk * 8 + 7; bi >= chunk * 8; bi--) {
                if (acc + s_hist[bi] >= KPRE) { bb = bi; break; }
                acc += s_hist[bi];
            }
            s_sel[0] = (uint32_t)bb; s_sel[1] = acc;
        }
        __syncthreads();
        pref = (pref << 11) | s_sel[0]; n_above = s_sel[1];
        __syncthreads();
    }
    // refine bits [9:0]
    {
        for (int i = tid; i < 2048; i += 256) s_hist[i] = 0;
        __syncthreads();
        for (uint32_t i = tid; i < M; i += 256) {
            uint32_t k = (uint32_t)(s_cand[i] >> 32);
            if ((k >> 10) == pref) atomicAdd(&s_hist[k & 0x3FFu], 1u);
        }
        __syncthreads();
        uint32_t cs = 0;
#pragma unroll
        for (int i = 0; i < 8; i++) cs += s_hist[tid * 8 + i];
        s_csum[tid] = cs;
        __syncthreads();
        if (tid == 0) {
            uint32_t acc = n_above; int chunk = 0;
            for (int cg = 255; cg >= 0; cg--) {
                if (acc + s_csum[cg] >= KPRE) { chunk = cg; break; }
                acc += s_csum[cg];
            }
            int bb = chunk * 8;
            for (int bi = chunk * 8 + 7; bi >= chunk * 8; bi--) {
                if (acc + s_hist[bi] >= KPRE) { bb = bi; break; }
                acc += s_hist[bi];
            }
            s_sel[0] = (uint32_t)bb;
        }
        __syncthreads();
    }
    uint32_t F = (pref << 10) | s_sel[0];

    // ================= compact qualifying (key >= F) into s_h64, rank-sort =================
    if (tid == 0) s_cnt = 0;
    __syncthreads();    // also retires last hist use of s_h64
    for (uint32_t i = tid; i < M; i += 256) {
        u64 c = s_cand[i];
        if ((uint32_t)(c >> 32) >= F) {
            uint32_t pos = atomicAdd(&s_cnt, 1u);
            if (pos < QCAP) s_h64[pos] = c;
        }
    }
    __syncthreads();
    uint32_t M2 = s_cnt; if (M2 > QCAP) M2 = QCAP;
    for (uint32_t i = tid; i < M2; i += 256) {
        u64 mine = s_h64[i];
        uint32_t rank = 0;
        for (uint32_t j = 0; j < M2; j++) rank += (s_h64[j] > mine);
        if (rank < KPRE) s_key[rank] = mine;
    }
    __syncthreads();

    // ================= extract top-256 =================
    u64 key = s_key[tid];
    uint32_t idx = ~(uint32_t)key;
    float scv = unmono((uint32_t)(key >> 32));
    float4 bj = g_boxes[(size_t)b * PNUM + idx];
    float aj = fmaxf(bj.z - bj.x, 0.f) * fmaxf(bj.w - bj.y, 0.f);
    s_box[tid]  = bj;
    s_area[tid] = aj;
    {
        bool valid = scv > 0.01f;
        uint32_t bal = __ballot_sync(0xFFFFFFFFu, valid);
        if (lane == 0) s_keep[wid] = bal;
    }
    // zero suppression matrix (reuse s_h64 region as 2048 u32 words)
    uint32_t* s_supp = (uint32_t*)s_h64;
    for (int i = tid; i < 2048; i += 256) s_supp[i] = 0;
    __syncthreads();

    // ================= suppression bitmatrix (warp-bounded rows, band-exact IoU) ==========
    {
        const int imax = wid * 32 + 32;    // rows this warp can be suppressed by
        for (int i = 0; i < imax; i++) {
            float4 bi = s_box[i];
            float wx = fmaxf(fminf(bi.z, bj.z) - fmaxf(bi.x, bj.x), 0.f);
            float wy = fmaxf(fminf(bi.w, bj.w) - fmaxf(bi.y, bj.y), 0.f);
            float inter = __fmul_rn(wx, wy);
            float uni = __fadd_rn(__fadd_rn(s_area[i], aj), -inter);
            float ut = fmaxf(uni, 1e-9f);
            float r  = __fmul_rn(0.45f, ut);
            bool gt  = tid > i;
            bool sup = gt && (inter > __fmul_rn(1.0001f, r));
            if (gt && !sup && inter >= __fmul_rn(0.9999f, r))
                sup = (inter / ut) > 0.45f;        // exact IEEE path, ~never taken
            uint32_t bal = __ballot_sync(0xFFFFFFFFu, sup);
            if (lane == 0) s_supp[i * 8 + wid] = bal;
        }
    }
    __syncthreads();

    // ================= serial greedy scan on warp 0 =================
    if (wid == 0) {
        uint32_t kw = (lane < 8) ? s_keep[lane] : 0u;
        for (int i = 0; i < KPRE - 1; i++) {
            uint32_t w = __shfl_sync(0xFFFFFFFFu, kw, i >> 5);
            if ((w >> (i & 31)) & 1u)
                kw &= ~s_supp[i * 8 + (lane & 7)];
        }
        if (lane < 8) s_keep[lane] = kw;
    }
    __syncthreads();

    // ================= compaction + output =================
    if (tid == 0) {
        uint32_t a = 0;
#pragma unroll
        for (int w2 = 0; w2 < 8; w2++) { s_wpre[w2] = a; a += __popc(s_keep[w2]); }
    }
    float* op = out + (size_t)pair * (TOPK * 5);
    for (int i = tid; i < TOPK * 5; i += 256) op[i] = 0.f;
    __syncthreads();

    uint32_t kwm = s_keep[wid];
    if ((kwm >> lane) & 1u) {
        uint32_t rank = s_wpre[wid] + __popc(kwm & ((1u << lane) - 1u));
        if (rank < TOPK) {
            float* r = op + (size_t)rank * 5;
            r[0] = scv;
            r[1] = bj.x; r[2] = bj.y; r[3] = bj.z; r[4] = bj.w;
        }
    }
}

// ------------------------------------------------------------------
extern "C" void kernel_launch(void* const* d_in, const int* in_sizes, int n_in,
                              void* d_out, int out_size) {
    const float* loc   = (const float*)d_in[0];
    const float* conf  = (const float*)d_in[1];
    const float* prior = (const float*)d_in[2];
    float* out = (float*)d_out;

    int total = BNUM * PNUM;
    prep_kernel<<<(total + 255) / 256, 256>>>(loc, conf, prior);
    topk_nms_kernel<<<NPAIR, 256>>>(out);
}